// round 13
// baseline (speedup 1.0000x reference)
#include <cuda_runtime.h>
#include <cuda_fp16.h>
#include <cuda_fp8.h>
#include <cstddef>

#define DIM1 100000
#define DIM2 100000
#define RANK 64
#define BATCH 262144

#define SCALE_F      256.0f
#define INV_SCALE_SQ (1.0f / 65536.0f)   // 2^-16, exact

// Half-rank tables in e4m3 (pre-scaled by 256): 32 ranks -> 32B/row = 2 uint4.
// q0 = ranks 0..31, q1 = ranks 32..63. 3.2MB each, all four L2-resident.
__device__ uint4 g_UTq0[(size_t)DIM1 * 2];
__device__ uint4 g_VTq0[(size_t)DIM2 * 2];
__device__ uint4 g_UTq1[(size_t)DIM1 * 2];
__device__ uint4 g_VTq1[(size_t)DIM2 * 2];
// Partial result: dot(ranks 0..31) + bias_U[i1] + bias_V[i2].
__device__ float g_aux[BATCH];

// ---------------------------------------------------------------------------
// 32x32 transpose+convert tile: src ranks [rank_off, rank_off+32) x dims
// [c0, c0+32) -> dst rows (32B fp8 per dim). 256 threads. Conflict-free:
// load  tile[r][tx], addr stride 33;
// store reads tile[4w+k][row], bank = (4w+k+row) mod 32: w0..7 x row0..3
// covers all 32 banks. Output: warp writes 128B contiguous.
// ---------------------------------------------------------------------------
__device__ __forceinline__ void transpose_tile32(
    const float* __restrict__ src, unsigned* __restrict__ dst,
    int rank_off, int c0, int tid, float (*tile)[33])
{
    int tx = tid & 31, ty = tid >> 5;          // ty 0..7
    #pragma unroll
    for (int j = 0; j < 4; ++j) {
        int r = ty + 8 * j;                    // 0..31
        tile[r][tx] = __ldcs(&src[(size_t)(rank_off + r) * DIM1 + (c0 + tx)]);
    }
    __syncthreads();
    int row = tid >> 3;                        // 0..31: dim within tile
    int w   = tid & 7;                         // 0..7 : 4-rank word
    float2 lo = make_float2(tile[4*w+0][row] * SCALE_F, tile[4*w+1][row] * SCALE_F);
    float2 hi = make_float2(tile[4*w+2][row] * SCALE_F, tile[4*w+3][row] * SCALE_F);
    unsigned p01 = __nv_cvt_float2_to_fp8x2(lo, __NV_SATFINITE, __NV_E4M3);
    unsigned p23 = __nv_cvt_float2_to_fp8x2(hi, __NV_SATFINITE, __NV_E4M3);
    dst[(size_t)(c0 + row) * 8 + w] = p01 | (p23 << 16);
}

// 16-term e4m3 dot (scaled domain), half2 HFMA2 accumulation.
__device__ __forceinline__ float dot16(uint4 a, uint4 c) {
    const __nv_fp8x2_storage_t* pa = (const __nv_fp8x2_storage_t*)&a;
    const __nv_fp8x2_storage_t* pc = (const __nv_fp8x2_storage_t*)&c;
    __half2 acc = __float2half2_rn(0.0f);
    #pragma unroll
    for (int k = 0; k < 8; ++k) {
        __half2_raw ra = __nv_cvt_fp8x2_to_halfraw2(pa[k], __NV_E4M3);
        __half2_raw rc = __nv_cvt_fp8x2_to_halfraw2(pc[k], __NV_E4M3);
        acc = __hfma2(*(__half2*)&ra, *(__half2*)&rc, acc);
    }
    float2 f = __half22float2(acc);
    return f.x + f.y;
}

// ---------------------------------------------------------------------------
// K1: transpose ranks 0..31 of U and V. 6250 blocks. Triggers PDL so K2
// launches into our tail.
// ---------------------------------------------------------------------------
__global__ void __launch_bounds__(256)
k1_transpose0(const float* __restrict__ U_w, const float* __restrict__ V_w) {
    __shared__ float tile[32][33];
    if (threadIdx.x == 0) cudaTriggerProgrammaticLaunchCompletion();
    int bx = blockIdx.x;
    const float* src = (bx < 3125) ? U_w : V_w;
    unsigned*    dst = (unsigned*)((bx < 3125) ? g_UTq0 : g_VTq0);
    int c0 = ((bx < 3125) ? bx : bx - 3125) * 32;
    transpose_tile32(src, dst, 0, c0, threadIdx.x, tile);
}

// ---------------------------------------------------------------------------
// K2: INTERLEAVED grid (7294 blocks; every 7th is a gather block).
//  - transpose blocks (6/7): ranks 32..63 -> q1. No dependency on K1:
//    run immediately, stream DRAM.
//  - gather blocks (1/7): half-dot over ranks 0..31 + both biases -> aux.
//    Wait on K1 via griddepsync; prologue (idx/bias loads) runs before it.
//  Co-residency fills the gather's latency bubbles with transpose streaming.
// ---------------------------------------------------------------------------
__global__ void __launch_bounds__(256)
k2_mix(const float* __restrict__ U_w, const float* __restrict__ V_w,
       const int2* __restrict__ xw,
       const float* __restrict__ bias_U, const float* __restrict__ bias_V) {
    __shared__ float tile[32][33];
    if (threadIdx.x == 0) cudaTriggerProgrammaticLaunchCompletion();
    int bx  = blockIdx.x;
    int grp = bx / 7, ph = bx % 7;

    if (ph == 6) {                       // ---- gather half 0 ----
        if (grp >= BATCH / 256) return;
        int b = grp * 256 + threadIdx.x;
        int2 p = __ldg(xw + b);
        int i1 = p.x, i2 = p.y;
        const uint4* u = g_UTq0 + (size_t)i1 * 2;
        const uint4* v = g_VTq0 + (size_t)i2 * 2;
        float bu = __ldg(bias_U + i1);
        float bv = __ldg(bias_V + i2);
        cudaGridDependencySynchronize();   // wait for K1 (q0 tables)
        uint4 a0 = __ldg(u), a1 = __ldg(u + 1);
        uint4 c0 = __ldg(v), c1 = __ldg(v + 1);
        float s = dot16(a0, c0) + dot16(a1, c1);
        g_aux[b] = s * INV_SCALE_SQ + bu + bv;
    } else {                             // ---- transpose ranks 32..63 ----
        int t = grp * 6 + ph;
        if (t >= 6250) return;
        const float* src = (t < 3125) ? U_w : V_w;
        unsigned*    dst = (unsigned*)((t < 3125) ? g_UTq1 : g_VTq1);
        int c0 = ((t < 3125) ? t : t - 3125) * 32;
        transpose_tile32(src, dst, 32, c0, threadIdx.x, tile);
    }
}

// ---------------------------------------------------------------------------
// K3 (PDL): half-dot over ranks 32..63 + aux -> out. 1 thread/element,
// MLP 4 table loads. Prologue (idx) overlaps K2's tail.
// ---------------------------------------------------------------------------
__global__ void __launch_bounds__(256)
k3_gather1(const int2* __restrict__ xw, float* __restrict__ out) {
    int b = blockIdx.x * 256 + threadIdx.x;
    int2 p = __ldg(xw + b);
    int i1 = p.x, i2 = p.y;
    const uint4* u = g_UTq1 + (size_t)i1 * 2;
    const uint4* v = g_VTq1 + (size_t)i2 * 2;
    cudaGridDependencySynchronize();       // wait for K2 (q1 tables + aux)
    uint4 a0 = __ldg(u), a1 = __ldg(u + 1);
    uint4 c0 = __ldg(v), c1 = __ldg(v + 1);
    float s = dot16(a0, c0) + dot16(a1, c1);
    out[b] = g_aux[b] + s * INV_SCALE_SQ;
}

// ---------------------------------------------------------------------------
// kernel_launch: K1 -> K2 (PDL) -> K3 (PDL). Three launches, no sync, no
// allocation, graph-capturable.
// Input order: x(int32, BATCH*2), U_w(f32), V_w(f32), bias_U, bias_V
// ---------------------------------------------------------------------------
extern "C" void kernel_launch(void* const* d_in, const int* in_sizes, int n_in,
                              void* d_out, int out_size) {
    const int2*  xw     = (const int2*)d_in[0];
    const float* U_w    = (const float*)d_in[1];
    const float* V_w    = (const float*)d_in[2];
    const float* bias_U = (const float*)d_in[3];
    const float* bias_V = (const float*)d_in[4];
    float*       out    = (float*)d_out;

    k1_transpose0<<<6250, 256>>>(U_w, V_w);

    cudaLaunchAttribute attrs[1];
    attrs[0].id = cudaLaunchAttributeProgrammaticStreamSerialization;
    attrs[0].val.programmaticStreamSerializationAllowed = 1;

    cudaLaunchConfig_t cfg = {};
    cfg.blockDim = dim3(256, 1, 1);
    cfg.dynamicSmemBytes = 0;
    cfg.stream = 0;
    cfg.attrs = attrs;
    cfg.numAttrs = 1;

    cfg.gridDim = dim3(7294, 1, 1);      // 1042 groups x 7 (6 transpose + 1 gather)
    cudaLaunchKernelEx(&cfg, k2_mix, U_w, V_w, xw, bias_U, bias_V);

    cfg.gridDim = dim3(BATCH / 256, 1, 1);   // 1024 blocks
    cudaLaunchKernelEx(&cfg, k3_gather1, xw, out);
}

// round 14
// speedup vs baseline: 1.2676x; 1.2676x over previous
#include <cuda_runtime.h>
#include <cuda_fp16.h>
#include <cuda_fp8.h>
#include <cstddef>

#define DIM1 100000
#define DIM2 100000
#define RANK 64
#define BATCH 262144

#define SCALE_F      256.0f
#define INV_SCALE_SQ (1.0f / 65536.0f)   // 2^-16, exact

// Transposed factor tables in e4m3 (pre-scaled by 256): (DIM, 64) row-major,
// 64B per row = 4 uint4. 6.4MB each -> both trivially L2-resident.
__device__ uint4 g_UTq[(size_t)DIM1 * 4];
__device__ uint4 g_VTq[(size_t)DIM2 * 4];

// ---------------------------------------------------------------------------
// Kernel 1 (PDL primary): transpose + fp32 -> e4m3(x256) convert.
// Tile 64 ranks x 128 dims, block 512. Each thread issues 4 independent
// float4 loads (64B in flight, 4x the scalar version) -- the transpose was
// measured latency-bound (half-size copy took equal time in R13), so wider
// per-thread MLP is the lever. 782 tiles per matrix; last tile (32 dims)
// guarded. Store path: thread -> (dim, 4-rank word), <=2-way smem conflicts,
// warp-contiguous 16B-chunk global stores.
// ---------------------------------------------------------------------------
__global__ void __launch_bounds__(512)
transpose_convert_kernel(const float* __restrict__ U_w,
                         const float* __restrict__ V_w) {
    __shared__ float tile[64][132];   // row stride 132 floats = 528B (16B-aligned)

    if (threadIdx.x == 0)
        cudaTriggerProgrammaticLaunchCompletion();

    const float* src = (blockIdx.z == 0) ? U_w : V_w;
    unsigned*    dst = (unsigned*)((blockIdx.z == 0) ? g_UTq : g_VTq);

    int c0  = blockIdx.x * 128;               // dim offset; last tile has 32 valid
    int tid = threadIdx.x;
    int wrp = tid >> 5, l = tid & 31;
    int nd  = DIM1 - c0;                      // valid dims in this tile (128 or 32)

    // Load: warp handles 4 rank-rows; lane loads float4 at dim 4l.
    {
        int d0 = 4 * l;
        bool ok = d0 < nd;                    // remainder is 32 (mult of 4): no partial float4
        #pragma unroll
        for (int j = 0; j < 4; ++j) {
            int r = wrp * 4 + j;              // 0..63
            float4 val = ok ? __ldcs((const float4*)(src + (size_t)r * DIM1 + c0 + d0))
                            : make_float4(0.f, 0.f, 0.f, 0.f);
            *(float4*)&tile[r][d0] = val;
        }
    }
    __syncthreads();

    // Convert+store: thread -> dim d = tid>>2 (0..127), words w0+4j (j=0..3).
    {
        int d  = tid >> 2;
        int w0 = tid & 3;
        if (d < nd) {
            #pragma unroll
            for (int j = 0; j < 4; ++j) {
                int w = w0 + 4 * j;           // 0..15: ranks 4w..4w+3
                float2 lo = make_float2(tile[4*w+0][d] * SCALE_F,
                                        tile[4*w+1][d] * SCALE_F);
                float2 hi = make_float2(tile[4*w+2][d] * SCALE_F,
                                        tile[4*w+3][d] * SCALE_F);
                unsigned p01 = __nv_cvt_float2_to_fp8x2(lo, __NV_SATFINITE, __NV_E4M3);
                unsigned p23 = __nv_cvt_float2_to_fp8x2(hi, __NV_SATFINITE, __NV_E4M3);
                dst[(size_t)(c0 + d) * 16 + w] = p01 | (p23 << 16);
            }
        }
    }
}

// 16-term e4m3 dot: decode fp8x2 -> half2, HFMA2 accumulate (scaled domain;
// values ~N(0,0.81), 32-term half partial sums well in range).
__device__ __forceinline__ float dot16(uint4 a, uint4 c) {
    const __nv_fp8x2_storage_t* pa = (const __nv_fp8x2_storage_t*)&a;
    const __nv_fp8x2_storage_t* pc = (const __nv_fp8x2_storage_t*)&c;
    __half2 acc = __float2half2_rn(0.0f);
    #pragma unroll
    for (int k = 0; k < 8; ++k) {
        __half2_raw ra = __nv_cvt_fp8x2_to_halfraw2(pa[k], __NV_E4M3);
        __half2_raw rc = __nv_cvt_fp8x2_to_halfraw2(pc[k], __NV_E4M3);
        acc = __hfma2(*(__half2*)&ra, *(__half2*)&rc, acc);
    }
    float2 f = __half22float2(acc);
    return f.x + f.y;
}

// ---------------------------------------------------------------------------
// Kernel 2 (PDL secondary) — R11-proven gather, verbatim: 2 lanes/element,
// 2 uint4 per table per lane (MLP 4), bias select-pointer load per lane,
// bias lifted by 2^16 (exact) through the 1-deep reduction.
// ---------------------------------------------------------------------------
__global__ void __launch_bounds__(256, 6)
gather_dot_kernel(const int2* __restrict__ xw,
                  const float* __restrict__ bias_U,
                  const float* __restrict__ bias_V,
                  float* __restrict__ out) {
    int gid  = blockIdx.x * blockDim.x + threadIdx.x;
    int b    = gid >> 1;        // 2 lanes per element
    int lane = gid & 1;

    // ---- prologue: independent of the transpose output ----
    int2 p = __ldg(xw + b);     // (i1, i2) int32 pair; warp = one 128B line
    int i1 = p.x, i2 = p.y;

    const float* bp = lane ? (bias_V + i2) : (bias_U + i1);
    float bias = __ldg(bp);

    unsigned lsl = (unsigned)lane << 5;   // 32B slice per lane
    const uint4* u = (const uint4*)((const char*)g_UTq + (((unsigned)i1 << 6) | lsl));
    const uint4* v = (const uint4*)((const char*)g_VTq + (((unsigned)i2 << 6) | lsl));

    // ---- wait for the transpose to fully complete ----
    cudaGridDependencySynchronize();

    uint4 a0 = __ldg(u);
    uint4 a1 = __ldg(u + 1);
    uint4 c0 = __ldg(v);
    uint4 c1 = __ldg(v + 1);

    float s = dot16(a0, c0) + dot16(a1, c1) + bias * 65536.0f;

    s += __shfl_xor_sync(0xffffffffu, s, 1);

    if (lane == 0) out[b] = s * INV_SCALE_SQ;
}

// ---------------------------------------------------------------------------
// kernel_launch: transpose (primary) then gather (PDL secondary). Two
// launches, no sync, no allocation, graph-capturable.
// Input order: x(int32, BATCH*2), U_w(f32), V_w(f32), bias_U, bias_V
// ---------------------------------------------------------------------------
extern "C" void kernel_launch(void* const* d_in, const int* in_sizes, int n_in,
                              void* d_out, int out_size) {
    const int2*  xw     = (const int2*)d_in[0];
    const float* U_w    = (const float*)d_in[1];
    const float* V_w    = (const float*)d_in[2];
    const float* bias_U = (const float*)d_in[3];
    const float* bias_V = (const float*)d_in[4];
    float*       out    = (float*)d_out;

    dim3 tgrid((DIM1 + 127) / 128, 1, 2);     // 782 x 2 tiles
    transpose_convert_kernel<<<tgrid, 512>>>(U_w, V_w);

    cudaLaunchAttribute attrs[1];
    attrs[0].id = cudaLaunchAttributeProgrammaticStreamSerialization;
    attrs[0].val.programmaticStreamSerializationAllowed = 1;

    cudaLaunchConfig_t cfg = {};
    cfg.gridDim  = dim3((BATCH * 2) / 256, 1, 1);   // exact: 2048 blocks
    cfg.blockDim = dim3(256, 1, 1);
    cfg.dynamicSmemBytes = 0;
    cfg.stream = 0;
    cfg.attrs = attrs;
    cfg.numAttrs = 1;

    cudaLaunchKernelEx(&cfg, gather_dot_kernel, xw, bias_U, bias_V, out);
}